// round 1
// baseline (speedup 1.0000x reference)
#include <cuda_runtime.h>

#define NB   8
#define NPTS 4096
#define KNN  8
#define DIM  128
#define PTS  32   // points per MLP block

// Scratch (static device globals are the allowed scratch mechanism)
__device__ float g_rel[NB * NPTS * KNN * 3];     // [point][k][3]
__device__ float g_W1q[DIM * DIM];               // [c/4][d][4] swizzle of W1[d][c]
__device__ float g_W2q[DIM * DIM];

// ---------------------------------------------------------------------------
// Weight swizzle: Wq[c4*512 + d*4 + j] = W[d*128 + c4*4 + j]
// Lets thread d fetch its 4 weights for channels c4*4..c4*4+3 as one LDG.128,
// fully coalesced across the warp.
// ---------------------------------------------------------------------------
__global__ void prep_weights(const float* __restrict__ W1,
                             const float* __restrict__ W2) {
    int i = blockIdx.x * blockDim.x + threadIdx.x;
    if (i >= DIM * DIM) return;
    int c4 = i >> 9;
    int d  = (i >> 2) & (DIM - 1);
    int j  = i & 3;
    int c  = c4 * 4 + j;
    g_W1q[i] = W1[d * DIM + c];
    g_W2q[i] = W2[d * DIM + c];
}

// ---------------------------------------------------------------------------
// KNN: one block = 256 queries of one batch; all 4096 points of the batch
// cached in smem as float4(x,y,z,|p|^2). Each thread keeps a sorted top-8 in
// registers. d2 = sq_i + sq_j - 2*dot matches the reference formula; strict
// '<' in the bubble preserves stable (lower-index-first) tie order.
// Writes rel = nbr - self directly (6 float4 per point).
// ---------------------------------------------------------------------------
__global__ void knn_kernel(const float* __restrict__ x) {
    extern __shared__ float4 pts[];   // NPTS * 16B = 64 KB
    const int b   = blockIdx.y;
    const int tid = threadIdx.x;
    const float* xb = x + (size_t)b * 3 * NPTS;

    for (int i = tid; i < NPTS; i += blockDim.x) {
        float xx = xb[i], yy = xb[NPTS + i], zz = xb[2 * NPTS + i];
        pts[i] = make_float4(xx, yy, zz, xx * xx + yy * yy + zz * zz);
    }
    __syncthreads();

    const int q = blockIdx.x * blockDim.x + tid;
    const float4 pq = pts[q];
    const float sqi = pq.w;

    float bd[KNN];
    int   bj[KNN];
#pragma unroll
    for (int s = 0; s < KNN; ++s) { bd[s] = 3.4e38f; bj[s] = 0; }

    for (int j = 0; j < NPTS; ++j) {
        float4 pj = pts[j];
        float dot = fmaf(pq.z, pj.z, fmaf(pq.y, pj.y, pq.x * pj.x));
        float d2  = fmaf(-2.0f, dot, sqi + pj.w);
        if (d2 < bd[KNN - 1] && j != q) {
            bd[KNN - 1] = d2; bj[KNN - 1] = j;
#pragma unroll
            for (int s = KNN - 1; s > 0; --s) {
                if (bd[s] < bd[s - 1]) {
                    float td = bd[s]; bd[s] = bd[s - 1]; bd[s - 1] = td;
                    int   tj = bj[s]; bj[s] = bj[s - 1]; bj[s - 1] = tj;
                }
            }
        }
    }

    float rel[KNN * 3];
#pragma unroll
    for (int k = 0; k < KNN; ++k) {
        float4 pn = pts[bj[k]];
        rel[k * 3 + 0] = pn.x - pq.x;
        rel[k * 3 + 1] = pn.y - pq.y;
        rel[k * 3 + 2] = pn.z - pq.z;
    }
    float4* dst = (float4*)(g_rel + (size_t)(b * NPTS + q) * (KNN * 3));
    const float4* src = (const float4*)rel;
#pragma unroll
    for (int i = 0; i < 6; ++i) dst[i] = src[i];
}

// ---------------------------------------------------------------------------
// MLP: block = 128 threads (thread == output channel d), PTS=32 points/block.
// Hidden state in smem laid out [c][k] (8 floats/row) -> inner loop reads h
// rows via broadcast LDS.128; weights via one coalesced LDG.128 per 4
// channels. Per 4 channels: 1 LDG + 8 LDS + 32 FFMA (FFMA-bound).
// ---------------------------------------------------------------------------
__device__ __forceinline__ void fma8(float acc[KNN], const float4* hr, float w) {
    float4 a = hr[0], b = hr[1];
    acc[0] = fmaf(a.x, w, acc[0]); acc[1] = fmaf(a.y, w, acc[1]);
    acc[2] = fmaf(a.z, w, acc[2]); acc[3] = fmaf(a.w, w, acc[3]);
    acc[4] = fmaf(b.x, w, acc[4]); acc[5] = fmaf(b.y, w, acc[5]);
    acc[6] = fmaf(b.z, w, acc[6]); acc[7] = fmaf(b.w, w, acc[7]);
}

__device__ __forceinline__ void layer128(float acc[KNN], const float* hs,
                                         const float4* __restrict__ Wq4, int d) {
#pragma unroll
    for (int k = 0; k < KNN; ++k) acc[k] = 0.0f;
#pragma unroll 4
    for (int c4 = 0; c4 < DIM / 4; ++c4) {
        float4 w = Wq4[c4 * DIM + d];
        const float4* hr = (const float4*)(hs + c4 * 32);
        fma8(acc, hr + 0, w.x);
        fma8(acc, hr + 2, w.y);
        fma8(acc, hr + 4, w.z);
        fma8(acc, hr + 6, w.w);
    }
}

__global__ void __launch_bounds__(128)
mlp_kernel(const float* __restrict__ W0, float* __restrict__ out) {
    __shared__ float W0s[DIM * 3];
    __shared__ float relbuf[PTS * KNN * 3];
    __shared__ float hsa[DIM * KNN];   // [c][k]
    __shared__ float hsb[DIM * KNN];
    __shared__ float obuf[DIM * PTS];

    const int tid = threadIdx.x;
    const int d   = tid;
    const int pid0 = blockIdx.x * PTS;
    const int b  = pid0 >> 12;          // / 4096
    const int n0 = pid0 & (NPTS - 1);

    for (int i = tid; i < DIM * 3; i += 128) W0s[i] = W0[i];
    const float* relg = g_rel + (size_t)pid0 * (KNN * 3);
    for (int i = tid; i < PTS * KNN * 3; i += 128) relbuf[i] = relg[i];
    __syncthreads();

    const float w0a = W0s[d * 3 + 0];
    const float w0b = W0s[d * 3 + 1];
    const float w0c = W0s[d * 3 + 2];
    const float4* W1q4 = (const float4*)g_W1q;
    const float4* W2q4 = (const float4*)g_W2q;

    for (int p = 0; p < PTS; ++p) {
        const float* rp = &relbuf[p * KNN * 3];

        // layer 0: 3 -> 128
        float h0[KNN];
#pragma unroll
        for (int k = 0; k < KNN; ++k) {
            float a = fmaf(rp[k * 3 + 2], w0c,
                      fmaf(rp[k * 3 + 1], w0b, rp[k * 3 + 0] * w0a));
            h0[k] = fmaxf(a, 0.0f);
        }
        *(float4*)&hsa[d * 8 + 0] = make_float4(h0[0], h0[1], h0[2], h0[3]);
        *(float4*)&hsa[d * 8 + 4] = make_float4(h0[4], h0[5], h0[6], h0[7]);
        __syncthreads();

        // layer 1: 128 -> 128
        float acc[KNN];
        layer128(acc, hsa, W1q4, d);
#pragma unroll
        for (int k = 0; k < KNN; ++k) acc[k] = fmaxf(acc[k], 0.0f);
        *(float4*)&hsb[d * 8 + 0] = make_float4(acc[0], acc[1], acc[2], acc[3]);
        *(float4*)&hsb[d * 8 + 4] = make_float4(acc[4], acc[5], acc[6], acc[7]);
        __syncthreads();

        // layer 2: 128 -> 128, then relu+max over k
        float acc2[KNN];
        layer128(acc2, hsb, W2q4, d);
        float m = fmaxf(fmaxf(fmaxf(acc2[0], acc2[1]), fmaxf(acc2[2], acc2[3])),
                        fmaxf(fmaxf(acc2[4], acc2[5]), fmaxf(acc2[6], acc2[7])));
        obuf[d * PTS + p] = fmaxf(m, 0.0f);
        __syncthreads();   // hsb free for next point
    }

    // coalesced flush: warp w owns channel rows d = w, w+4, ... ; 128B per warp-store
    const int w    = tid >> 5;
    const int lane = tid & 31;
    float* obase = out + (size_t)b * DIM * NPTS + n0;
    for (int dd = w; dd < DIM; dd += 4) {
        obase[(size_t)dd * NPTS + lane] = obuf[dd * PTS + lane];
    }
}

// ---------------------------------------------------------------------------
extern "C" void kernel_launch(void* const* d_in, const int* in_sizes, int n_in,
                              void* d_out, int out_size) {
    const float* x  = (const float*)d_in[0];
    const float* W0 = (const float*)d_in[1];
    const float* W1 = (const float*)d_in[2];
    const float* W2 = (const float*)d_in[3];
    float* out = (float*)d_out;

    // 64 KB dynamic smem for the point cache (above the 48 KB static limit)
    cudaFuncSetAttribute(knn_kernel, cudaFuncAttributeMaxDynamicSharedMemorySize,
                         NPTS * (int)sizeof(float4));

    prep_weights<<<(DIM * DIM + 255) / 256, 256>>>(W1, W2);
    knn_kernel<<<dim3(NPTS / 256, NB), 256, NPTS * sizeof(float4)>>>(x);
    mlp_kernel<<<NB * NPTS / PTS, 128>>>(W0, out);
}

// round 3
// speedup vs baseline: 2.2898x; 2.2898x over previous
#include <cuda_runtime.h>
#include <cuda_bf16.h>
#include <cstdint>

#define NB    8
#define NPTS  4096
#define KNN   8
#define DIM   128
#define TPTS  16                   // points per tile (16*8 = 128 rows)
#define NTILES (NB * NPTS / TPTS)  // 2048
#define GRID_MLP 148

// ---------------- scratch (device globals = allowed scratch) ----------------
__device__ float g_rel[NB * NPTS * KNN * 3];          // [point][k][3]
// Fragment-major weights: [layer][kt 0..7][nt 0..15][lane 0..31] -> uint4
// {bhi0, bhi1, blo0, blo1}; bhi0 = bf16x2(Whi[n][k0], Whi[n][k0+1]),
// bhi1 = k0+8/9; n = nt*8 + lane/4; k0 = kt*16 + (lane%4)*2.  128 KB total.
__device__ __align__(16) uint4 g_Bw[2 * 8 * 16 * 32];

// ---------------- helpers ---------------------------------------------------
__device__ __forceinline__ uint32_t pack_bf16x2(float lo, float hi) {
    uint32_t r;
    asm("cvt.rn.satfinite.bf16x2.f32 %0, %1, %2;" : "=r"(r) : "f"(hi), "f"(lo));
    return r;
}
// split pair (a=elem0/lo, b=elem1/hi) into hi/lo bf16x2 words
__device__ __forceinline__ void split2(float a, float b, uint32_t& hi, uint32_t& lo) {
    uint32_t hp = pack_bf16x2(a, b);
    float ha = __uint_as_float(hp << 16);
    float hb = __uint_as_float(hp & 0xFFFF0000u);
    hi = hp;
    lo = pack_bf16x2(a - ha, b - hb);
}
__device__ __forceinline__ void mma16816(float* c, const uint32_t* a,
                                         uint32_t b0, uint32_t b1) {
    asm volatile(
        "mma.sync.aligned.m16n8k16.row.col.f32.bf16.bf16.f32 "
        "{%0,%1,%2,%3}, {%4,%5,%6,%7}, {%8,%9}, {%0,%1,%2,%3};"
        : "+f"(c[0]), "+f"(c[1]), "+f"(c[2]), "+f"(c[3])
        : "r"(a[0]), "r"(a[1]), "r"(a[2]), "r"(a[3]), "r"(b0), "r"(b1));
}

// ---------------------------------------------------------------------------
// Weight prep: split W1/W2 into hi/lo bf16, emit fragment-major uint4 layout.
// One thread per (layer, kt, nt, lane) = 8192 threads.
// ---------------------------------------------------------------------------
__global__ void prep_weights(const float* __restrict__ W1,
                             const float* __restrict__ W2) {
    int i = blockIdx.x * blockDim.x + threadIdx.x;
    if (i >= 2 * 8 * 16 * 32) return;
    int lane = i & 31;
    int nt   = (i >> 5) & 15;
    int kt   = (i >> 9) & 7;
    int lay  = i >> 12;
    const float* W = lay ? W2 : W1;      // [d][c] row-major
    int n  = nt * 8 + (lane >> 2);
    int k0 = kt * 16 + (lane & 3) * 2;
    float w[4] = { W[n * DIM + k0],     W[n * DIM + k0 + 1],
                   W[n * DIM + k0 + 8], W[n * DIM + k0 + 9] };
    float hi[4], lo[4];
#pragma unroll
    for (int j = 0; j < 4; ++j) {
        hi[j] = __bfloat162float(__float2bfloat16_rn(w[j]));
        lo[j] = w[j] - hi[j];
    }
    uint4 v;
    v.x = pack_bf16x2(hi[0], hi[1]);
    v.y = pack_bf16x2(hi[2], hi[3]);
    v.z = pack_bf16x2(lo[0], lo[1]);
    v.w = pack_bf16x2(lo[2], lo[3]);
    g_Bw[i] = v;
}

// ---------------------------------------------------------------------------
// KNN (unchanged: rel_err 0.0 in R1)
// ---------------------------------------------------------------------------
__global__ void knn_kernel(const float* __restrict__ x) {
    extern __shared__ float4 pts[];   // 64 KB
    const int b   = blockIdx.y;
    const int tid = threadIdx.x;
    const float* xb = x + (size_t)b * 3 * NPTS;

    for (int i = tid; i < NPTS; i += blockDim.x) {
        float xx = xb[i], yy = xb[NPTS + i], zz = xb[2 * NPTS + i];
        pts[i] = make_float4(xx, yy, zz, xx * xx + yy * yy + zz * zz);
    }
    __syncthreads();

    const int q = blockIdx.x * blockDim.x + tid;
    const float4 pq = pts[q];
    const float sqi = pq.w;

    float bd[KNN];
    int   bj[KNN];
#pragma unroll
    for (int s = 0; s < KNN; ++s) { bd[s] = 3.4e38f; bj[s] = 0; }

    for (int j = 0; j < NPTS; ++j) {
        float4 pj = pts[j];
        float dot = fmaf(pq.z, pj.z, fmaf(pq.y, pj.y, pq.x * pj.x));
        float d2  = fmaf(-2.0f, dot, sqi + pj.w);
        if (d2 < bd[KNN - 1] && j != q) {
            bd[KNN - 1] = d2; bj[KNN - 1] = j;
#pragma unroll
            for (int s = KNN - 1; s > 0; --s) {
                if (bd[s] < bd[s - 1]) {
                    float td = bd[s]; bd[s] = bd[s - 1]; bd[s - 1] = td;
                    int   tj = bj[s]; bj[s] = bj[s - 1]; bj[s - 1] = tj;
                }
            }
        }
    }

    float rel[KNN * 3];
#pragma unroll
    for (int k = 0; k < KNN; ++k) {
        float4 pn = pts[bj[k]];
        rel[k * 3 + 0] = pn.x - pq.x;
        rel[k * 3 + 1] = pn.y - pq.y;
        rel[k * 3 + 2] = pn.z - pq.z;
    }
    float4* dst = (float4*)(g_rel + (size_t)(b * NPTS + q) * (KNN * 3));
    const float4* src = (const float4*)rel;
#pragma unroll
    for (int i = 0; i < 6; ++i) dst[i] = src[i];
}

// ---------------------------------------------------------------------------
// MLP: persistent blocks, 256 threads = 8 warps. Warp w owns rows
// w*16..w*16+15 of the 128-row tile = points 2w (rows 0-7) and 2w+1 (8-15).
// Layer chain lives entirely in registers; weights (fragment-major, hi+lo
// interleaved) in smem, one LDS.128 per (kt,nt) feeds 3 MMAs.
// ---------------------------------------------------------------------------
__global__ void __launch_bounds__(256, 1)
mlp_kernel(const float* __restrict__ W0, float* __restrict__ out) {
    extern __shared__ __align__(16) uint4 wsm[];   // 8192 uint4 = 128 KB
    __shared__ float W0s[DIM * 3];
    __shared__ float obuf[DIM * TPTS];

    const int tid  = threadIdx.x;
    const int w    = tid >> 5;
    const int lane = tid & 31;
    const int r0   = lane >> 2;        // 0..7
    const int q4   = lane & 3;         // 0..3

    for (int i = tid; i < 2 * 8 * 16 * 32; i += 256) wsm[i] = g_Bw[i];
    for (int i = tid; i < DIM * 3; i += 256) W0s[i] = W0[i];
    __syncthreads();

    uint32_t ahi[8][4], alo[8][4];
    float acc[16][4];

    for (int tile = blockIdx.x; tile < NTILES; tile += GRID_MLP) {
        const int pid0 = tile * TPTS;
        const int b    = pid0 >> 12;
        const int n0   = pid0 & (NPTS - 1);

        // ---- layer 0: rel(3) -> h(128) directly as A fragments ----
        const float* ra = g_rel + (size_t)(pid0 + 2 * w)     * (KNN * 3) + r0 * 3;
        const float* rb = g_rel + (size_t)(pid0 + 2 * w + 1) * (KNN * 3) + r0 * 3;
        const float ax = ra[0], ay = ra[1], az = ra[2];
        const float bx = rb[0], by = rb[1], bz = rb[2];
#pragma unroll
        for (int kt = 0; kt < 8; ++kt) {
            const int cb = kt * 16 + q4 * 2;
            float hA[4], hB[4];
#pragma unroll
            for (int j = 0; j < 4; ++j) {
                const int c = cb + (j & 1) + (j >> 1) * 8;
                const float w0 = W0s[c * 3], w1 = W0s[c * 3 + 1], w2 = W0s[c * 3 + 2];
                hA[j] = fmaxf(fmaf(az, w2, fmaf(ay, w1, ax * w0)), 0.0f);
                hB[j] = fmaxf(fmaf(bz, w2, fmaf(by, w1, bx * w0)), 0.0f);
            }
            split2(hA[0], hA[1], ahi[kt][0], alo[kt][0]);
            split2(hB[0], hB[1], ahi[kt][1], alo[kt][1]);
            split2(hA[2], hA[3], ahi[kt][2], alo[kt][2]);
            split2(hB[2], hB[3], ahi[kt][3], alo[kt][3]);
        }

        // ---- layer 1: MMAs ----
#pragma unroll
        for (int nt = 0; nt < 16; ++nt)
#pragma unroll
            for (int j = 0; j < 4; ++j) acc[nt][j] = 0.0f;
#pragma unroll
        for (int kt = 0; kt < 8; ++kt) {
            const uint4* bp = wsm + (0 * 8 + kt) * 16 * 32 + lane;
#pragma unroll
            for (int nt = 0; nt < 16; ++nt) {
                uint4 bw = bp[nt * 32];
                mma16816(acc[nt], ahi[kt], bw.x, bw.y);
                mma16816(acc[nt], alo[kt], bw.x, bw.y);
                mma16816(acc[nt], ahi[kt], bw.z, bw.w);
            }
        }

        // ---- relu + split: C fragments -> next layer's A fragments ----
#pragma unroll
        for (int j = 0; j < 8; ++j) {
            split2(fmaxf(acc[2 * j][0], 0.f),     fmaxf(acc[2 * j][1], 0.f),     ahi[j][0], alo[j][0]);
            split2(fmaxf(acc[2 * j][2], 0.f),     fmaxf(acc[2 * j][3], 0.f),     ahi[j][1], alo[j][1]);
            split2(fmaxf(acc[2 * j + 1][0], 0.f), fmaxf(acc[2 * j + 1][1], 0.f), ahi[j][2], alo[j][2]);
            split2(fmaxf(acc[2 * j + 1][2], 0.f), fmaxf(acc[2 * j + 1][3], 0.f), ahi[j][3], alo[j][3]);
        }

        // ---- layer 2: MMAs ----
#pragma unroll
        for (int nt = 0; nt < 16; ++nt)
#pragma unroll
            for (int j = 0; j < 4; ++j) acc[nt][j] = 0.0f;
#pragma unroll
        for (int kt = 0; kt < 8; ++kt) {
            const uint4* bp = wsm + (1 * 8 + kt) * 16 * 32 + lane;
#pragma unroll
            for (int nt = 0; nt < 16; ++nt) {
                uint4 bw = bp[nt * 32];
                mma16816(acc[nt], ahi[kt], bw.x, bw.y);
                mma16816(acc[nt], alo[kt], bw.x, bw.y);
                mma16816(acc[nt], ahi[kt], bw.z, bw.w);
            }
        }

        // ---- relu + max over 8 neighbors (rows) via shfl, stage to obuf ----
#pragma unroll
        for (int nt = 0; nt < 16; ++nt) {
            float v0 = fmaxf(acc[nt][0], 0.f), v1 = fmaxf(acc[nt][1], 0.f);
            float v2 = fmaxf(acc[nt][2], 0.f), v3 = fmaxf(acc[nt][3], 0.f);
#pragma unroll
            for (int m = 4; m <= 16; m <<= 1) {
                v0 = fmaxf(v0, __shfl_xor_sync(0xffffffffu, v0, m));
                v1 = fmaxf(v1, __shfl_xor_sync(0xffffffffu, v1, m));
                v2 = fmaxf(v2, __shfl_xor_sync(0xffffffffu, v2, m));
                v3 = fmaxf(v3, __shfl_xor_sync(0xffffffffu, v3, m));
            }
            if (lane < 4) {
                const int d0 = nt * 8 + q4 * 2;
                obuf[d0 * TPTS + 2 * w]           = v0;   // point 2w,   col d0
                obuf[(d0 + 1) * TPTS + 2 * w]     = v1;
                obuf[d0 * TPTS + 2 * w + 1]       = v2;   // point 2w+1
                obuf[(d0 + 1) * TPTS + 2 * w + 1] = v3;
            }
        }
        __syncthreads();

        // ---- coalesced flush ----
        float* ob = out + (size_t)b * DIM * NPTS + n0;
        for (int i = tid; i < DIM * TPTS; i += 256) {
            ob[(size_t)(i >> 4) * NPTS + (i & 15)] = obuf[i];
        }
        __syncthreads();
    }
}

// ---------------------------------------------------------------------------
extern "C" void kernel_launch(void* const* d_in, const int* in_sizes, int n_in,
                              void* d_out, int out_size) {
    const float* x  = (const float*)d_in[0];
    const float* W0 = (const float*)d_in[1];
    const float* W1 = (const float*)d_in[2];
    const float* W2 = (const float*)d_in[3];
    float* out = (float*)d_out;

    const int knn_smem = NPTS * (int)sizeof(float4);   // 64 KB
    const int mlp_smem = 2 * 8 * 16 * 32 * 16;         // 128 KB
    cudaFuncSetAttribute(knn_kernel, cudaFuncAttributeMaxDynamicSharedMemorySize, knn_smem);
    cudaFuncSetAttribute(mlp_kernel, cudaFuncAttributeMaxDynamicSharedMemorySize, mlp_smem);

    prep_weights<<<(2 * 8 * 16 * 32 + 255) / 256, 256>>>(W1, W2);
    knn_kernel<<<dim3(NPTS / 256, NB), 256, knn_smem>>>(x);
    mlp_kernel<<<GRID_MLP, 256, mlp_smem>>>(W0, out);
}

// round 4
// speedup vs baseline: 2.4794x; 1.0828x over previous
#include <cuda_runtime.h>
#include <cuda_fp16.h>
#include <cuda_bf16.h>
#include <cstdint>

#define NB    8
#define NPTS  4096
#define KNN   8
#define DIM   128
#define TPTS  16                   // points per tile (16*8 = 128 rows)
#define NTILES (NB * NPTS / TPTS)  // 2048
#define GRID_MLP 148

// ---------------- scratch (device globals = allowed scratch) ----------------
__device__ float g_rel[NB * NPTS * KNN * 3];          // [point][k][3]
// Fragment-major fp16 weights: [layer][kt 0..7][nt 0..15][lane 0..31] -> uint2
// {b0, b1}; b0 = f16x2(W[n][k0], W[n][k0+1]), b1 = k0+8/9;
// n = nt*8 + lane/4; k0 = kt*16 + (lane%4)*2.  64 KB total.
__device__ __align__(8) uint2 g_Bw[2 * 8 * 16 * 32];

// ---------------- helpers ---------------------------------------------------
// split pair (a=elem0, b=elem1) into hi/lo f16x2 words (2-term fp16 decomp)
__device__ __forceinline__ void split2h(float a, float b, uint32_t& hi, uint32_t& lo) {
    __half2 h = __floats2half2_rn(a, b);
    float2 hf = __half22float2(h);
    __half2 l = __floats2half2_rn(a - hf.x, b - hf.y);
    hi = *(uint32_t*)&h;
    lo = *(uint32_t*)&l;
}
__device__ __forceinline__ void mma16816(float* c, const uint32_t* a,
                                         uint32_t b0, uint32_t b1) {
    asm volatile(
        "mma.sync.aligned.m16n8k16.row.col.f32.f16.f16.f32 "
        "{%0,%1,%2,%3}, {%4,%5,%6,%7}, {%8,%9}, {%0,%1,%2,%3};"
        : "+f"(c[0]), "+f"(c[1]), "+f"(c[2]), "+f"(c[3])
        : "r"(a[0]), "r"(a[1]), "r"(a[2]), "r"(a[3]), "r"(b0), "r"(b1));
}

// ---------------------------------------------------------------------------
// Weight prep: fp32 -> fp16 fragment-major uint2 layout. 8192 threads.
// ---------------------------------------------------------------------------
__global__ void prep_weights(const float* __restrict__ W1,
                             const float* __restrict__ W2) {
    int i = blockIdx.x * blockDim.x + threadIdx.x;
    if (i >= 2 * 8 * 16 * 32) return;
    int lane = i & 31;
    int nt   = (i >> 5) & 15;
    int kt   = (i >> 9) & 7;
    int lay  = i >> 12;
    const float* W = lay ? W2 : W1;      // [d][c] row-major
    int n  = nt * 8 + (lane >> 2);
    int k0 = kt * 16 + (lane & 3) * 2;
    __half2 b0 = __floats2half2_rn(W[n * DIM + k0],     W[n * DIM + k0 + 1]);
    __half2 b1 = __floats2half2_rn(W[n * DIM + k0 + 8], W[n * DIM + k0 + 9]);
    uint2 v;
    v.x = *(uint32_t*)&b0;
    v.y = *(uint32_t*)&b1;
    g_Bw[i] = v;
}

// ---------------------------------------------------------------------------
// KNN (unchanged: exact match in R1/R3)
// ---------------------------------------------------------------------------
__global__ void knn_kernel(const float* __restrict__ x) {
    extern __shared__ float4 pts[];   // 64 KB
    const int b   = blockIdx.y;
    const int tid = threadIdx.x;
    const float* xb = x + (size_t)b * 3 * NPTS;

    for (int i = tid; i < NPTS; i += blockDim.x) {
        float xx = xb[i], yy = xb[NPTS + i], zz = xb[2 * NPTS + i];
        pts[i] = make_float4(xx, yy, zz, xx * xx + yy * yy + zz * zz);
    }
    __syncthreads();

    const int q = blockIdx.x * blockDim.x + tid;
    const float4 pq = pts[q];
    const float sqi = pq.w;

    float bd[KNN];
    int   bj[KNN];
#pragma unroll
    for (int s = 0; s < KNN; ++s) { bd[s] = 3.4e38f; bj[s] = 0; }

#pragma unroll 4
    for (int j = 0; j < NPTS; ++j) {
        float4 pj = pts[j];
        float dot = fmaf(pq.z, pj.z, fmaf(pq.y, pj.y, pq.x * pj.x));
        float d2  = fmaf(-2.0f, dot, sqi + pj.w);
        if (d2 < bd[KNN - 1] && j != q) {
            bd[KNN - 1] = d2; bj[KNN - 1] = j;
#pragma unroll
            for (int s = KNN - 1; s > 0; --s) {
                if (bd[s] < bd[s - 1]) {
                    float td = bd[s]; bd[s] = bd[s - 1]; bd[s - 1] = td;
                    int   tj = bj[s]; bj[s] = bj[s - 1]; bj[s - 1] = tj;
                }
            }
        }
    }

    float rel[KNN * 3];
#pragma unroll
    for (int k = 0; k < KNN; ++k) {
        float4 pn = pts[bj[k]];
        rel[k * 3 + 0] = pn.x - pq.x;
        rel[k * 3 + 1] = pn.y - pq.y;
        rel[k * 3 + 2] = pn.z - pq.z;
    }
    float4* dst = (float4*)(g_rel + (size_t)(b * NPTS + q) * (KNN * 3));
    const float4* src = (const float4*)rel;
#pragma unroll
    for (int i = 0; i < 6; ++i) dst[i] = src[i];
}

// ---------------------------------------------------------------------------
// MLP: persistent, 8 warps/block, warp owns 16 rows = 2 points.
// A = fp16 hi+lo fragments (registers); B = single fp16 in smem (uint2/frag).
// Per (kt,nt): 1 LDS.64 + 2 HMMA.
// ---------------------------------------------------------------------------
__global__ void __launch_bounds__(256, 1)
mlp_kernel(const float* __restrict__ W0, float* __restrict__ out) {
    extern __shared__ __align__(8) uint2 wsm[];   // 8192 uint2 = 64 KB
    __shared__ float W0s[DIM * 3];
    __shared__ float obuf[DIM * TPTS];

    const int tid  = threadIdx.x;
    const int w    = tid >> 5;
    const int lane = tid & 31;
    const int r0   = lane >> 2;        // 0..7
    const int q4   = lane & 3;         // 0..3

    for (int i = tid; i < 2 * 8 * 16 * 32; i += 256) wsm[i] = g_Bw[i];
    for (int i = tid; i < DIM * 3; i += 256) W0s[i] = W0[i];
    __syncthreads();

    uint32_t ahi[8][4], alo[8][4];
    float acc[16][4];

    for (int tile = blockIdx.x; tile < NTILES; tile += GRID_MLP) {
        const int pid0 = tile * TPTS;
        const int b    = pid0 >> 12;
        const int n0   = pid0 & (NPTS - 1);

        // ---- layer 0: rel(3) -> h(128) directly as A fragments ----
        const float* ra = g_rel + (size_t)(pid0 + 2 * w)     * (KNN * 3) + r0 * 3;
        const float* rb = g_rel + (size_t)(pid0 + 2 * w + 1) * (KNN * 3) + r0 * 3;
        const float ax = ra[0], ay = ra[1], az = ra[2];
        const float bx = rb[0], by = rb[1], bz = rb[2];
#pragma unroll
        for (int kt = 0; kt < 8; ++kt) {
            const int cb = kt * 16 + q4 * 2;
            float hA[4], hB[4];
#pragma unroll
            for (int j = 0; j < 4; ++j) {
                const int c = cb + (j & 1) + (j >> 1) * 8;
                const float w0 = W0s[c * 3], w1 = W0s[c * 3 + 1], w2 = W0s[c * 3 + 2];
                hA[j] = fmaxf(fmaf(az, w2, fmaf(ay, w1, ax * w0)), 0.0f);
                hB[j] = fmaxf(fmaf(bz, w2, fmaf(by, w1, bx * w0)), 0.0f);
            }
            split2h(hA[0], hA[1], ahi[kt][0], alo[kt][0]);
            split2h(hB[0], hB[1], ahi[kt][1], alo[kt][1]);
            split2h(hA[2], hA[3], ahi[kt][2], alo[kt][2]);
            split2h(hB[2], hB[3], ahi[kt][3], alo[kt][3]);
        }

        // ---- layer 1: MMAs ----
#pragma unroll
        for (int nt = 0; nt < 16; ++nt)
#pragma unroll
            for (int j = 0; j < 4; ++j) acc[nt][j] = 0.0f;
#pragma unroll
        for (int kt = 0; kt < 8; ++kt) {
            const uint2* bp = wsm + (0 * 8 + kt) * 16 * 32 + lane;
#pragma unroll
            for (int nt = 0; nt < 16; ++nt) {
                uint2 bw = bp[nt * 32];
                mma16816(acc[nt], ahi[kt], bw.x, bw.y);
                mma16816(acc[nt], alo[kt], bw.x, bw.y);
            }
        }

        // ---- relu + split: C fragments -> next layer's A fragments ----
#pragma unroll
        for (int j = 0; j < 8; ++j) {
            split2h(fmaxf(acc[2 * j][0], 0.f),     fmaxf(acc[2 * j][1], 0.f),     ahi[j][0], alo[j][0]);
            split2h(fmaxf(acc[2 * j][2], 0.f),     fmaxf(acc[2 * j][3], 0.f),     ahi[j][1], alo[j][1]);
            split2h(fmaxf(acc[2 * j + 1][0], 0.f), fmaxf(acc[2 * j + 1][1], 0.f), ahi[j][2], alo[j][2]);
            split2h(fmaxf(acc[2 * j + 1][2], 0.f), fmaxf(acc[2 * j + 1][3], 0.f), ahi[j][3], alo[j][3]);
        }

        // ---- layer 2: MMAs ----
#pragma unroll
        for (int nt = 0; nt < 16; ++nt)
#pragma unroll
            for (int j = 0; j < 4; ++j) acc[nt][j] = 0.0f;
#pragma unroll
        for (int kt = 0; kt < 8; ++kt) {
            const uint2* bp = wsm + (1 * 8 + kt) * 16 * 32 + lane;
#pragma unroll
            for (int nt = 0; nt < 16; ++nt) {
                uint2 bw = bp[nt * 32];
                mma16816(acc[nt], ahi[kt], bw.x, bw.y);
                mma16816(acc[nt], alo[kt], bw.x, bw.y);
            }
        }

        // ---- relu + max over 8 neighbors via shfl, stage to obuf ----
#pragma unroll
        for (int nt = 0; nt < 16; ++nt) {
            float v0 = fmaxf(acc[nt][0], 0.f), v1 = fmaxf(acc[nt][1], 0.f);
            float v2 = fmaxf(acc[nt][2], 0.f), v3 = fmaxf(acc[nt][3], 0.f);
#pragma unroll
            for (int m = 4; m <= 16; m <<= 1) {
                v0 = fmaxf(v0, __shfl_xor_sync(0xffffffffu, v0, m));
                v1 = fmaxf(v1, __shfl_xor_sync(0xffffffffu, v1, m));
                v2 = fmaxf(v2, __shfl_xor_sync(0xffffffffu, v2, m));
                v3 = fmaxf(v3, __shfl_xor_sync(0xffffffffu, v3, m));
            }
            if (lane < 4) {
                const int d0 = nt * 8 + q4 * 2;
                obuf[d0 * TPTS + 2 * w]           = v0;   // point 2w,   col d0
                obuf[(d0 + 1) * TPTS + 2 * w]     = v1;
                obuf[d0 * TPTS + 2 * w + 1]       = v2;   // point 2w+1
                obuf[(d0 + 1) * TPTS + 2 * w + 1] = v3;
            }
        }
        __syncthreads();

        // ---- coalesced flush ----
        float* ob = out + (size_t)b * DIM * NPTS + n0;
        for (int i = tid; i < DIM * TPTS; i += 256) {
            ob[(size_t)(i >> 4) * NPTS + (i & 15)] = obuf[i];
        }
        __syncthreads();
    }
}

// no-op: shifts ncu's captured-launch index onto mlp_kernel (4 launches/call)
__global__ void noop_kernel() {}

// ---------------------------------------------------------------------------
extern "C" void kernel_launch(void* const* d_in, const int* in_sizes, int n_in,
                              void* d_out, int out_size) {
    const float* x  = (const float*)d_in[0];
    const float* W0 = (const float*)d_in[1];
    const float* W1 = (const float*)d_in[2];
    const float* W2 = (const float*)d_in[3];
    float* out = (float*)d_out;

    const int knn_smem = NPTS * (int)sizeof(float4);   // 64 KB
    const int mlp_smem = 2 * 8 * 16 * 32 * 8;          // 64 KB
    cudaFuncSetAttribute(knn_kernel, cudaFuncAttributeMaxDynamicSharedMemorySize, knn_smem);
    cudaFuncSetAttribute(mlp_kernel, cudaFuncAttributeMaxDynamicSharedMemorySize, mlp_smem);

    prep_weights<<<(2 * 8 * 16 * 32 + 255) / 256, 256>>>(W1, W2);
    knn_kernel<<<dim3(NPTS / 256, NB), 256, knn_smem>>>(x);
    mlp_kernel<<<GRID_MLP, 256, mlp_smem>>>(W0, out);
    noop_kernel<<<1, 32>>>();
}

// round 5
// speedup vs baseline: 2.7266x; 1.0997x over previous
#include <cuda_runtime.h>
#include <cuda_fp16.h>
#include <cstdint>

#define NB    8
#define NPTS  4096
#define KNN   8
#define DIM   128
#define TPTS  16                   // points per tile (16*8 = 128 rows)
#define NTILES (NB * NPTS / TPTS)  // 2048
#define GRID_MLP 296               // 2 persistent blocks per SM

// ---------------- scratch (device globals = allowed scratch) ----------------
__device__ float g_rel[NB * NPTS * KNN * 3];          // [point][k][3]
// Fragment-major fp16 weights: [layer][kt 0..7][nt 0..15][lane 0..31] -> uint2
// {b0, b1}; b0 = f16x2(W[n][k0], W[n][k0+1]), b1 = k0+8/9;
// n = nt*8 + lane/4; k0 = kt*16 + (lane%4)*2.  64 KB total.
__device__ __align__(8) uint2 g_Bw[2 * 8 * 16 * 32];

// ---------------- helpers ---------------------------------------------------
__device__ __forceinline__ uint32_t packh2(float a, float b) {
    __half2 h = __floats2half2_rn(a, b);
    return *(uint32_t*)&h;
}
__device__ __forceinline__ void mma16816(float* c, const uint32_t* a,
                                         uint32_t b0, uint32_t b1) {
    asm volatile(
        "mma.sync.aligned.m16n8k16.row.col.f32.f16.f16.f32 "
        "{%0,%1,%2,%3}, {%4,%5,%6,%7}, {%8,%9}, {%0,%1,%2,%3};"
        : "+f"(c[0]), "+f"(c[1]), "+f"(c[2]), "+f"(c[3])
        : "r"(a[0]), "r"(a[1]), "r"(a[2]), "r"(a[3]), "r"(b0), "r"(b1));
}

// ---------------------------------------------------------------------------
// Weight prep: fp32 -> fp16 fragment-major uint2 layout. 8192 threads.
// ---------------------------------------------------------------------------
__global__ void prep_weights(const float* __restrict__ W1,
                             const float* __restrict__ W2) {
    int i = blockIdx.x * blockDim.x + threadIdx.x;
    if (i >= 2 * 8 * 16 * 32) return;
    int lane = i & 31;
    int nt   = (i >> 5) & 15;
    int kt   = (i >> 9) & 7;
    int lay  = i >> 12;
    const float* W = lay ? W2 : W1;      // [d][c] row-major
    int n  = nt * 8 + (lane >> 2);
    int k0 = kt * 16 + (lane & 3) * 2;
    uint2 v;
    v.x = packh2(W[n * DIM + k0],     W[n * DIM + k0 + 1]);
    v.y = packh2(W[n * DIM + k0 + 8], W[n * DIM + k0 + 9]);
    g_Bw[i] = v;
}

// ---------------------------------------------------------------------------
// KNN (unchanged: exact match since R1)
// ---------------------------------------------------------------------------
__global__ void knn_kernel(const float* __restrict__ x) {
    extern __shared__ float4 pts[];   // 64 KB
    const int b   = blockIdx.y;
    const int tid = threadIdx.x;
    const float* xb = x + (size_t)b * 3 * NPTS;

    for (int i = tid; i < NPTS; i += blockDim.x) {
        float xx = xb[i], yy = xb[NPTS + i], zz = xb[2 * NPTS + i];
        pts[i] = make_float4(xx, yy, zz, xx * xx + yy * yy + zz * zz);
    }
    __syncthreads();

    const int q = blockIdx.x * blockDim.x + tid;
    const float4 pq = pts[q];
    const float sqi = pq.w;

    float bd[KNN];
    int   bj[KNN];
#pragma unroll
    for (int s = 0; s < KNN; ++s) { bd[s] = 3.4e38f; bj[s] = 0; }

#pragma unroll 4
    for (int j = 0; j < NPTS; ++j) {
        float4 pj = pts[j];
        float dot = fmaf(pq.z, pj.z, fmaf(pq.y, pj.y, pq.x * pj.x));
        float d2  = fmaf(-2.0f, dot, sqi + pj.w);
        if (d2 < bd[KNN - 1] && j != q) {
            bd[KNN - 1] = d2; bj[KNN - 1] = j;
#pragma unroll
            for (int s = KNN - 1; s > 0; --s) {
                if (bd[s] < bd[s - 1]) {
                    float td = bd[s]; bd[s] = bd[s - 1]; bd[s - 1] = td;
                    int   tj = bj[s]; bj[s] = bj[s - 1]; bj[s - 1] = tj;
                }
            }
        }
    }

    float rel[KNN * 3];
#pragma unroll
    for (int k = 0; k < KNN; ++k) {
        float4 pn = pts[bj[k]];
        rel[k * 3 + 0] = pn.x - pq.x;
        rel[k * 3 + 1] = pn.y - pq.y;
        rel[k * 3 + 2] = pn.z - pq.z;
    }
    float4* dst = (float4*)(g_rel + (size_t)(b * NPTS + q) * (KNN * 3));
    const float4* src = (const float4*)rel;
#pragma unroll
    for (int i = 0; i < 6; ++i) dst[i] = src[i];
}

// ---------------------------------------------------------------------------
// MLP: persistent, 2 blocks/SM x 8 warps, warp owns 16 rows = 2 points.
// A = single fp16 fragments (hi-only; W-rounding dominates error anyway).
// N processed in 4 groups of 4 n8-tiles to keep acc registers at 16.
// ---------------------------------------------------------------------------
__global__ void __launch_bounds__(256, 2)
mlp_kernel(const float* __restrict__ W0, float* __restrict__ out) {
    extern __shared__ __align__(8) uint2 wsm[];   // 8192 uint2 = 64 KB
    __shared__ float W0s[DIM * 3];
    __shared__ float obuf[DIM * TPTS];

    const int tid  = threadIdx.x;
    const int w    = tid >> 5;
    const int lane = tid & 31;
    const int r0   = lane >> 2;        // 0..7
    const int q4   = lane & 3;         // 0..3

    for (int i = tid; i < 2 * 8 * 16 * 32; i += 256) wsm[i] = g_Bw[i];
    for (int i = tid; i < DIM * 3; i += 256) W0s[i] = W0[i];
    __syncthreads();

    uint32_t ahi[8][4];    // layer-1 A fragments
    uint32_t nahi[8][4];   // layer-2 A fragments

    for (int tile = blockIdx.x; tile < NTILES; tile += GRID_MLP) {
        const int pid0 = tile * TPTS;
        const int b    = pid0 >> 12;
        const int n0   = pid0 & (NPTS - 1);

        // ---- layer 0: rel(3) -> h(128) directly as fp16 A fragments ----
        const float* ra = g_rel + (size_t)(pid0 + 2 * w)     * (KNN * 3) + r0 * 3;
        const float* rb = g_rel + (size_t)(pid0 + 2 * w + 1) * (KNN * 3) + r0 * 3;
        const float ax = ra[0], ay = ra[1], az = ra[2];
        const float bx = rb[0], by = rb[1], bz = rb[2];
#pragma unroll
        for (int kt = 0; kt < 8; ++kt) {
            const int cb = kt * 16 + q4 * 2;
            float hA[4], hB[4];
#pragma unroll
            for (int j = 0; j < 4; ++j) {
                const int c = cb + (j & 1) + (j >> 1) * 8;
                const float w0 = W0s[c * 3], w1 = W0s[c * 3 + 1], w2 = W0s[c * 3 + 2];
                hA[j] = fmaxf(fmaf(az, w2, fmaf(ay, w1, ax * w0)), 0.0f);
                hB[j] = fmaxf(fmaf(bz, w2, fmaf(by, w1, bx * w0)), 0.0f);
            }
            ahi[kt][0] = packh2(hA[0], hA[1]);
            ahi[kt][1] = packh2(hB[0], hB[1]);
            ahi[kt][2] = packh2(hA[2], hA[3]);
            ahi[kt][3] = packh2(hB[2], hB[3]);
        }

        // ---- layer 1: 4 N-groups of 4 n8-tiles ----
#pragma unroll
        for (int g = 0; g < 4; ++g) {
            float acc[4][4];
#pragma unroll
            for (int i = 0; i < 4; ++i)
#pragma unroll
                for (int j = 0; j < 4; ++j) acc[i][j] = 0.0f;
#pragma unroll
            for (int kt = 0; kt < 8; ++kt) {
                const uint2* bp = wsm + kt * 512 + (4 * g) * 32 + lane;
#pragma unroll
                for (int i = 0; i < 4; ++i) {
                    uint2 bw = bp[i * 32];
                    mma16816(acc[i], ahi[kt], bw.x, bw.y);
                }
            }
            // relu + pack: nt pair (4g+2j, 4g+2j+1) -> layer-2 A frag kt'=2g+j
#pragma unroll
            for (int j = 0; j < 2; ++j) {
                nahi[2 * g + j][0] = packh2(fmaxf(acc[2 * j][0], 0.f),     fmaxf(acc[2 * j][1], 0.f));
                nahi[2 * g + j][1] = packh2(fmaxf(acc[2 * j][2], 0.f),     fmaxf(acc[2 * j][3], 0.f));
                nahi[2 * g + j][2] = packh2(fmaxf(acc[2 * j + 1][0], 0.f), fmaxf(acc[2 * j + 1][1], 0.f));
                nahi[2 * g + j][3] = packh2(fmaxf(acc[2 * j + 1][2], 0.f), fmaxf(acc[2 * j + 1][3], 0.f));
            }
        }

        // ---- layer 2 + relu + neighbor-max epilogue, same N-grouping ----
#pragma unroll
        for (int g = 0; g < 4; ++g) {
            float acc[4][4];
#pragma unroll
            for (int i = 0; i < 4; ++i)
#pragma unroll
                for (int j = 0; j < 4; ++j) acc[i][j] = 0.0f;
#pragma unroll
            for (int kt = 0; kt < 8; ++kt) {
                const uint2* bp = wsm + (8 + kt) * 512 + (4 * g) * 32 + lane;
#pragma unroll
                for (int i = 0; i < 4; ++i) {
                    uint2 bw = bp[i * 32];
                    mma16816(acc[i], nahi[kt], bw.x, bw.y);
                }
            }
#pragma unroll
            for (int i = 0; i < 4; ++i) {
                const int nt = 4 * g + i;
                float v0 = fmaxf(acc[i][0], 0.f), v1 = fmaxf(acc[i][1], 0.f);
                float v2 = fmaxf(acc[i][2], 0.f), v3 = fmaxf(acc[i][3], 0.f);
#pragma unroll
                for (int m = 4; m <= 16; m <<= 1) {
                    v0 = fmaxf(v0, __shfl_xor_sync(0xffffffffu, v0, m));
                    v1 = fmaxf(v1, __shfl_xor_sync(0xffffffffu, v1, m));
                    v2 = fmaxf(v2, __shfl_xor_sync(0xffffffffu, v2, m));
                    v3 = fmaxf(v3, __shfl_xor_sync(0xffffffffu, v3, m));
                }
                if (lane < 4) {
                    const int d0 = nt * 8 + q4 * 2;
                    obuf[d0 * TPTS + 2 * w]           = v0;   // point 2w,   col d0
                    obuf[(d0 + 1) * TPTS + 2 * w]     = v1;
                    obuf[d0 * TPTS + 2 * w + 1]       = v2;   // point 2w+1
                    obuf[(d0 + 1) * TPTS + 2 * w + 1] = v3;
                }
            }
        }
        __syncthreads();

        // ---- coalesced flush ----
        float* ob = out + (size_t)b * DIM * NPTS + n0;
        for (int i = tid; i < DIM * TPTS; i += 256) {
            ob[(size_t)(i >> 4) * NPTS + (i & 15)] = obuf[i];
        }
        __syncthreads();
    }
}

// no-op: with launch order (prep, knn, noop, mlp), ncu's captured launch #15
// (15 % 4 == 3) lands on mlp_kernel.
__global__ void noop_kernel() {}

// ---------------------------------------------------------------------------
extern "C" void kernel_launch(void* const* d_in, const int* in_sizes, int n_in,
                              void* d_out, int out_size) {
    const float* x  = (const float*)d_in[0];
    const float* W0 = (const float*)d_in[1];
    const float* W1 = (const float*)d_in[2];
    const float* W2 = (const float*)d_in[3];
    float* out = (float*)d_out;

    const int knn_smem = NPTS * (int)sizeof(float4);   // 64 KB
    const int mlp_smem = 2 * 8 * 16 * 32 * 8;          // 64 KB
    cudaFuncSetAttribute(knn_kernel, cudaFuncAttributeMaxDynamicSharedMemorySize, knn_smem);
    cudaFuncSetAttribute(mlp_kernel, cudaFuncAttributeMaxDynamicSharedMemorySize, mlp_smem);

    prep_weights<<<(2 * 8 * 16 * 32 + 255) / 256, 256>>>(W1, W2);
    knn_kernel<<<dim3(NPTS / 256, NB), 256, knn_smem>>>(x);
    noop_kernel<<<1, 32>>>();
    mlp_kernel<<<GRID_MLP, 256, mlp_smem>>>(W0, out);
}

// round 6
// speedup vs baseline: 3.2694x; 1.1991x over previous
#include <cuda_runtime.h>
#include <cuda_fp16.h>
#include <cstdint>

#define NB    8
#define NPTS  4096
#define KNN   8
#define DIM   128
#define TPTS  16                   // points per MLP tile (16*8 = 128 rows)
#define NTILES (NB * NPTS / TPTS)  // 2048
#define GRID_MLP 296               // 2 persistent blocks per SM
#define JC    4                    // KNN j-split factor
#define CHUNK (NPTS / JC)          // 1024

// ---------------- scratch (device globals = allowed scratch) ----------------
__device__ float g_rel[NB * NPTS * KNN * 3];          // [point][k][3]
__device__ __align__(16) float g_pd[NB * NPTS * JC * KNN];  // partial top-8 d2
__device__ __align__(16) int   g_pi[NB * NPTS * JC * KNN];  // partial top-8 idx
// Fragment-major fp16 weights: [layer][kt][nt][lane] -> uint2 (64 KB)
__device__ __align__(8) uint2 g_Bw[2 * 8 * 16 * 32];

// ---------------- helpers ---------------------------------------------------
__device__ __forceinline__ uint32_t packh2(float a, float b) {
    __half2 h = __floats2half2_rn(a, b);
    return *(uint32_t*)&h;
}
__device__ __forceinline__ void mma16816(float* c, const uint32_t* a,
                                         uint32_t b0, uint32_t b1) {
    asm volatile(
        "mma.sync.aligned.m16n8k16.row.col.f32.f16.f16.f32 "
        "{%0,%1,%2,%3}, {%4,%5,%6,%7}, {%8,%9}, {%0,%1,%2,%3};"
        : "+f"(c[0]), "+f"(c[1]), "+f"(c[2]), "+f"(c[3])
        : "r"(a[0]), "r"(a[1]), "r"(a[2]), "r"(a[3]), "r"(b0), "r"(b1));
}

// ---------------------------------------------------------------------------
// KNN scan: block = 256 queries x one 1024-point j-chunk. grid (16, 8, 4).
// Per-thread sorted top-8 over the chunk; partials to gmem (sorted asc,
// stable lower-index-first via strict '<'). Arithmetic identical to R1.
// ---------------------------------------------------------------------------
__global__ void __launch_bounds__(256)
knn_scan(const float* __restrict__ x) {
    __shared__ float4 pts[CHUNK];   // 16 KB
    const int b     = blockIdx.y;
    const int jbase = blockIdx.z * CHUNK;
    const int tid   = threadIdx.x;
    const float* xb = x + (size_t)b * 3 * NPTS;

    for (int i = tid; i < CHUNK; i += 256) {
        int j = jbase + i;
        float xx = xb[j], yy = xb[NPTS + j], zz = xb[2 * NPTS + j];
        pts[i] = make_float4(xx, yy, zz, xx * xx + yy * yy + zz * zz);
    }
    __syncthreads();

    const int q = blockIdx.x * 256 + tid;
    const float qx = xb[q], qy = xb[NPTS + q], qz = xb[2 * NPTS + q];
    const float sqi = qx * qx + qy * qy + qz * qz;
    const int qloc = q - jbase;     // in [0,CHUNK) only for the owning chunk

    float bd[KNN];
    int   bj[KNN];
#pragma unroll
    for (int s = 0; s < KNN; ++s) { bd[s] = 3.4e38f; bj[s] = 0; }

#pragma unroll 8
    for (int i = 0; i < CHUNK; ++i) {
        float4 pj = pts[i];
        float dot = fmaf(qz, pj.z, fmaf(qy, pj.y, qx * pj.x));
        float d2  = fmaf(-2.0f, dot, sqi + pj.w);
        if (d2 < bd[KNN - 1] && i != qloc) {
            bd[KNN - 1] = d2; bj[KNN - 1] = jbase + i;
#pragma unroll
            for (int s = KNN - 1; s > 0; --s) {
                if (bd[s] < bd[s - 1]) {
                    float td = bd[s]; bd[s] = bd[s - 1]; bd[s - 1] = td;
                    int   tj = bj[s]; bj[s] = bj[s - 1]; bj[s - 1] = tj;
                }
            }
        }
    }

    const int base = ((b * NPTS + q) * JC + blockIdx.z) * KNN;
    float4* pd = (float4*)(g_pd + base);
    int4*   pi = (int4*)(g_pi + base);
    pd[0] = make_float4(bd[0], bd[1], bd[2], bd[3]);
    pd[1] = make_float4(bd[4], bd[5], bd[6], bd[7]);
    pi[0] = make_int4(bj[0], bj[1], bj[2], bj[3]);
    pi[1] = make_int4(bj[4], bj[5], bj[6], bj[7]);
}

// ---------------------------------------------------------------------------
// KNN merge: thread per query. Stream the 4 sorted partial lists in chunk
// order (ascending index ranges -> strict '<' keeps exact stable tie order),
// keep top-8, gather neighbor coords, write rel.
// ---------------------------------------------------------------------------
__global__ void __launch_bounds__(256)
knn_merge(const float* __restrict__ x) {
    const int qi = blockIdx.x * 256 + threadIdx.x;   // 0..32767
    const int b  = qi >> 12;
    const int q  = qi & (NPTS - 1);
    const float* xb = x + (size_t)b * 3 * NPTS;

    const float4* pd = (const float4*)(g_pd + (size_t)qi * (JC * KNN));
    const int4*   pi = (const int4*)(g_pi + (size_t)qi * (JC * KNN));

    float bd[KNN];
    int   bj[KNN];
#pragma unroll
    for (int s = 0; s < KNN; ++s) { bd[s] = 3.4e38f; bj[s] = 0; }

#pragma unroll
    for (int v = 0; v < JC * KNN / 4; ++v) {
        float4 d4 = pd[v];
        int4   i4 = pi[v];
        float dv[4] = { d4.x, d4.y, d4.z, d4.w };
        int   iv[4] = { i4.x, i4.y, i4.z, i4.w };
#pragma unroll
        for (int t = 0; t < 4; ++t) {
            float d2 = dv[t]; int idx = iv[t];
            if (d2 < bd[KNN - 1]) {
                bd[KNN - 1] = d2; bj[KNN - 1] = idx;
#pragma unroll
                for (int s = KNN - 1; s > 0; --s) {
                    if (bd[s] < bd[s - 1]) {
                        float td = bd[s]; bd[s] = bd[s - 1]; bd[s - 1] = td;
                        int   tj = bj[s]; bj[s] = bj[s - 1]; bj[s - 1] = tj;
                    }
                }
            }
        }
    }

    const float qx = xb[q], qy = xb[NPTS + q], qz = xb[2 * NPTS + q];
    float rel[KNN * 3];
#pragma unroll
    for (int k = 0; k < KNN; ++k) {
        int j = bj[k];
        rel[k * 3 + 0] = xb[j] - qx;
        rel[k * 3 + 1] = xb[NPTS + j] - qy;
        rel[k * 3 + 2] = xb[2 * NPTS + j] - qz;
    }
    float4* dst = (float4*)(g_rel + (size_t)qi * (KNN * 3));
    const float4* src = (const float4*)rel;
#pragma unroll
    for (int i = 0; i < 6; ++i) dst[i] = src[i];
}

// ---------------------------------------------------------------------------
// Weight prep: fp32 -> fp16 fragment-major uint2 layout. 8192 threads.
// ---------------------------------------------------------------------------
__global__ void prep_weights(const float* __restrict__ W1,
                             const float* __restrict__ W2) {
    int i = blockIdx.x * blockDim.x + threadIdx.x;
    if (i >= 2 * 8 * 16 * 32) return;
    int lane = i & 31;
    int nt   = (i >> 5) & 15;
    int kt   = (i >> 9) & 7;
    int lay  = i >> 12;
    const float* W = lay ? W2 : W1;      // [d][c] row-major
    int n  = nt * 8 + (lane >> 2);
    int k0 = kt * 16 + (lane & 3) * 2;
    uint2 v;
    v.x = packh2(W[n * DIM + k0],     W[n * DIM + k0 + 1]);
    v.y = packh2(W[n * DIM + k0 + 8], W[n * DIM + k0 + 9]);
    g_Bw[i] = v;
}

// ---------------------------------------------------------------------------
// MLP (unchanged from R5: 83.6us, 2 blocks/SM)
// ---------------------------------------------------------------------------
__global__ void __launch_bounds__(256, 2)
mlp_kernel(const float* __restrict__ W0, float* __restrict__ out) {
    extern __shared__ __align__(8) uint2 wsm[];   // 64 KB
    __shared__ float W0s[DIM * 3];
    __shared__ float obuf[DIM * TPTS];

    const int tid  = threadIdx.x;
    const int w    = tid >> 5;
    const int lane = tid & 31;
    const int r0   = lane >> 2;
    const int q4   = lane & 3;

    for (int i = tid; i < 2 * 8 * 16 * 32; i += 256) wsm[i] = g_Bw[i];
    for (int i = tid; i < DIM * 3; i += 256) W0s[i] = W0[i];
    __syncthreads();

    uint32_t ahi[8][4];
    uint32_t nahi[8][4];

    for (int tile = blockIdx.x; tile < NTILES; tile += GRID_MLP) {
        const int pid0 = tile * TPTS;
        const int b    = pid0 >> 12;
        const int n0   = pid0 & (NPTS - 1);

        const float* ra = g_rel + (size_t)(pid0 + 2 * w)     * (KNN * 3) + r0 * 3;
        const float* rb = g_rel + (size_t)(pid0 + 2 * w + 1) * (KNN * 3) + r0 * 3;
        const float ax = ra[0], ay = ra[1], az = ra[2];
        const float bx = rb[0], by = rb[1], bz = rb[2];
#pragma unroll
        for (int kt = 0; kt < 8; ++kt) {
            const int cb = kt * 16 + q4 * 2;
            float hA[4], hB[4];
#pragma unroll
            for (int j = 0; j < 4; ++j) {
                const int c = cb + (j & 1) + (j >> 1) * 8;
                const float w0 = W0s[c * 3], w1 = W0s[c * 3 + 1], w2 = W0s[c * 3 + 2];
                hA[j] = fmaxf(fmaf(az, w2, fmaf(ay, w1, ax * w0)), 0.0f);
                hB[j] = fmaxf(fmaf(bz, w2, fmaf(by, w1, bx * w0)), 0.0f);
            }
            ahi[kt][0] = packh2(hA[0], hA[1]);
            ahi[kt][1] = packh2(hB[0], hB[1]);
            ahi[kt][2] = packh2(hA[2], hA[3]);
            ahi[kt][3] = packh2(hB[2], hB[3]);
        }

#pragma unroll
        for (int g = 0; g < 4; ++g) {
            float acc[4][4];
#pragma unroll
            for (int i = 0; i < 4; ++i)
#pragma unroll
                for (int j = 0; j < 4; ++j) acc[i][j] = 0.0f;
#pragma unroll
            for (int kt = 0; kt < 8; ++kt) {
                const uint2* bp = wsm + kt * 512 + (4 * g) * 32 + lane;
#pragma unroll
                for (int i = 0; i < 4; ++i) {
                    uint2 bw = bp[i * 32];
                    mma16816(acc[i], ahi[kt], bw.x, bw.y);
                }
            }
#pragma unroll
            for (int j = 0; j < 2; ++j) {
                nahi[2 * g + j][0] = packh2(fmaxf(acc[2 * j][0], 0.f),     fmaxf(acc[2 * j][1], 0.f));
                nahi[2 * g + j][1] = packh2(fmaxf(acc[2 * j][2], 0.f),     fmaxf(acc[2 * j][3], 0.f));
                nahi[2 * g + j][2] = packh2(fmaxf(acc[2 * j + 1][0], 0.f), fmaxf(acc[2 * j + 1][1], 0.f));
                nahi[2 * g + j][3] = packh2(fmaxf(acc[2 * j + 1][2], 0.f), fmaxf(acc[2 * j + 1][3], 0.f));
            }
        }

#pragma unroll
        for (int g = 0; g < 4; ++g) {
            float acc[4][4];
#pragma unroll
            for (int i = 0; i < 4; ++i)
#pragma unroll
                for (int j = 0; j < 4; ++j) acc[i][j] = 0.0f;
#pragma unroll
            for (int kt = 0; kt < 8; ++kt) {
                const uint2* bp = wsm + (8 + kt) * 512 + (4 * g) * 32 + lane;
#pragma unroll
                for (int i = 0; i < 4; ++i) {
                    uint2 bw = bp[i * 32];
                    mma16816(acc[i], nahi[kt], bw.x, bw.y);
                }
            }
#pragma unroll
            for (int i = 0; i < 4; ++i) {
                const int nt = 4 * g + i;
                float v0 = fmaxf(acc[i][0], 0.f), v1 = fmaxf(acc[i][1], 0.f);
                float v2 = fmaxf(acc[i][2], 0.f), v3 = fmaxf(acc[i][3], 0.f);
#pragma unroll
                for (int m = 4; m <= 16; m <<= 1) {
                    v0 = fmaxf(v0, __shfl_xor_sync(0xffffffffu, v0, m));
                    v1 = fmaxf(v1, __shfl_xor_sync(0xffffffffu, v1, m));
                    v2 = fmaxf(v2, __shfl_xor_sync(0xffffffffu, v2, m));
                    v3 = fmaxf(v3, __shfl_xor_sync(0xffffffffu, v3, m));
                }
                if (lane < 4) {
                    const int d0 = nt * 8 + q4 * 2;
                    obuf[d0 * TPTS + 2 * w]           = v0;
                    obuf[(d0 + 1) * TPTS + 2 * w]     = v1;
                    obuf[d0 * TPTS + 2 * w + 1]       = v2;
                    obuf[(d0 + 1) * TPTS + 2 * w + 1] = v3;
                }
            }
        }
        __syncthreads();

        float* ob = out + (size_t)b * DIM * NPTS + n0;
        for (int i = tid; i < DIM * TPTS; i += 256) {
            ob[(size_t)(i >> 4) * NPTS + (i & 15)] = obuf[i];
        }
        __syncthreads();
    }
}

// no-op: with 5 launches/call, ncu's captured launch #15 (15 % 5 == 0) lands
// on the FIRST launch -> knn_scan.
__global__ void noop_kernel() {}

// ---------------------------------------------------------------------------
extern "C" void kernel_launch(void* const* d_in, const int* in_sizes, int n_in,
                              void* d_out, int out_size) {
    const float* x  = (const float*)d_in[0];
    const float* W0 = (const float*)d_in[1];
    const float* W1 = (const float*)d_in[2];
    const float* W2 = (const float*)d_in[3];
    float* out = (float*)d_out;

    const int mlp_smem = 2 * 8 * 16 * 32 * 8;          // 64 KB
    cudaFuncSetAttribute(mlp_kernel, cudaFuncAttributeMaxDynamicSharedMemorySize, mlp_smem);

    knn_scan<<<dim3(NPTS / 256, NB, JC), 256>>>(x);
    prep_weights<<<(2 * 8 * 16 * 32 + 255) / 256, 256>>>(W1, W2);
    knn_merge<<<NB * NPTS / 256, 256>>>(x);
    noop_kernel<<<1, 32>>>();
    mlp_kernel<<<GRID_MLP, 256, mlp_smem>>>(W0, out);
}